// round 9
// baseline (speedup 1.0000x reference)
#include <cuda_runtime.h>

__device__ __forceinline__ float4 vqc_one(float4 e0, float4 e1, float4 e2,
                                          float4 n0, float4 n1, float4 n2) {
    float t[12] = {e0.x, e0.y, e0.z, e0.w,
                   e1.x, e1.y, e1.z, e1.w,
                   e2.x, e2.y, e2.z, e2.w};
    float x[4], y[4], z[4];
#pragma unroll
    for (int q = 0; q < 4; q++) {
        float s0, c0, s1, c1, s2, c2;
        __sincosf(t[3 * q + 0], &s0, &c0);
        __sincosf(t[3 * q + 1], &s1, &c1);
        __sincosf(t[3 * q + 2], &s2, &c2);
        float cc = c0 * c1;
        x[q] = cc * c2 - s0 * s2;
        y[q] = cc * s2 + s0 * c2;
        z[q] = -c0 * s1;
    }
    float z01   = z[0] * z[1];
    float z23   = z[2] * z[3];
    float z012  = z01 * z[2];
    float z123  = z[1] * z23;
    float z0123 = z01 * z23;
    float x01   = x[0] * x[1];

    float4 o;
    o.x = n0.x * x01           + n0.y * (x[0] * y[1] * z23)         + n0.z * z123;
    o.y = n0.w * (x[1] * x[2]) + n1.x * (z[0] * y[1] * x[2])        + n1.y * z01;
    o.z = n1.z * (x[2] * x[3]) + n1.w * (z01 * y[2] * x[3])         + n2.x * z012;
    o.w = n2.y * (x01 * x[3])  - n2.z * (y[0] * y[1] * z[2] * y[3]) + n2.w * z0123;
    return o;
}

// Persistent, one resident wave at 5 blocks/SM (48-reg class), unroll-2 for ILP.
__global__ __launch_bounds__(256, 5) void vqc_fused(const float4* __restrict__ enc,
                                                    const float* __restrict__ w,
                                                    float4* __restrict__ out,
                                                    int B) {
    __shared__ __align__(16) float sn[12];
    if (threadIdx.x < 4) {
        int q = threadIdx.x;
        float st, ct, sl, cl;
        __sincosf(w[q * 3 + 0], &st, &ct);
        __sincosf(w[q * 3 + 2], &sl, &cl);
        sn[q * 3 + 0] = -st * cl;
        sn[q * 3 + 1] =  st * sl;
        sn[q * 3 + 2] =  ct;
    }
    __syncthreads();
    const float4* n4 = (const float4*)sn;
    const float4 n0 = n4[0], n1 = n4[1], n2 = n4[2];

    const int nthreads = gridDim.x * blockDim.x;
    const int pairs = (B + 1) >> 1;

    for (int g = blockIdx.x * blockDim.x + threadIdx.x; g < pairs; g += nthreads) {
        const int i0 = 2 * g;
        const float4* p = enc + 3 * i0;

        // Front-load both items' vectors: 6 independent LDG.128 in flight.
        float4 a0 = __ldcs(p + 0);
        float4 a1 = __ldcs(p + 1);
        float4 a2 = __ldcs(p + 2);
        const bool has2 = (i0 + 1 < B);
        float4 b0, b1, b2;
        if (has2) {
            b0 = __ldcs(p + 3);
            b1 = __ldcs(p + 4);
            b2 = __ldcs(p + 5);
        }

        // Two independent chains -> ILP 2 across every MUFU/FMA latency.
        float4 oA = vqc_one(a0, a1, a2, n0, n1, n2);
        __stcs(&out[i0], oA);
        if (has2) {
            float4 oB = vqc_one(b0, b1, b2, n0, n1, n2);
            __stcs(&out[i0 + 1], oB);
        }
    }
}

extern "C" void kernel_launch(void* const* d_in, const int* in_sizes, int n_in,
                              void* d_out, int out_size) {
    int ei = 0, wi = 1;
    if (n_in >= 2 && in_sizes[0] < in_sizes[1]) { ei = 1; wi = 0; }
    const float* enc = (const float*)d_in[ei];
    const float* w   = (const float*)d_in[wi];
    int B = in_sizes[ei] / 12;

    const int threads = 256;
    const int max_blocks = 152 * 5;   // exactly one resident wave at 48 regs
    int pairs = (B + 1) / 2;
    int need = (pairs + threads - 1) / threads;
    int blocks = need < max_blocks ? need : max_blocks;

    vqc_fused<<<blocks, threads>>>((const float4*)enc, w, (float4*)d_out, B);
}

// round 10
// speedup vs baseline: 1.1805x; 1.1805x over previous
#include <cuda_runtime.h>
#include <cstdint>

#define NSTAGE 3
#define TILE 256                       // items per tile
#define TILE_VEC (TILE * 3)            // float4s per tile
#define TILE_BYTES (TILE * 48)         // 12288 B

__device__ __forceinline__ unsigned smem_u32(const void* p) {
    return (unsigned)__cvta_generic_to_shared(p);
}

__device__ __forceinline__ void mbar_init(unsigned mbar, unsigned cnt) {
    asm volatile("mbarrier.init.shared.b64 [%0], %1;" :: "r"(mbar), "r"(cnt) : "memory");
}
__device__ __forceinline__ void mbar_expect_tx(unsigned mbar, unsigned bytes) {
    asm volatile("mbarrier.arrive.expect_tx.shared.b64 _, [%0], %1;"
                 :: "r"(mbar), "r"(bytes) : "memory");
}
__device__ __forceinline__ void tma_bulk_g2s(unsigned dst, const void* src,
                                             unsigned bytes, unsigned mbar) {
    asm volatile("cp.async.bulk.shared::cta.global.mbarrier::complete_tx::bytes "
                 "[%0], [%1], %2, [%3];"
                 :: "r"(dst), "l"(src), "r"(bytes), "r"(mbar) : "memory");
}
__device__ __forceinline__ void mbar_wait(unsigned mbar, unsigned parity) {
    asm volatile(
        "{\n\t.reg .pred P;\n"
        "W%=:\n\t"
        "mbarrier.try_wait.parity.shared.b64 P, [%0], %1;\n\t"
        "@P bra D%=;\n\t"
        "bra W%=;\n"
        "D%=:\n\t}"
        :: "r"(mbar), "r"(parity) : "memory");
}

__device__ __forceinline__ float4 vqc_one(float4 e0, float4 e1, float4 e2,
                                          float4 n0, float4 n1, float4 n2) {
    float t[12] = {e0.x, e0.y, e0.z, e0.w,
                   e1.x, e1.y, e1.z, e1.w,
                   e2.x, e2.y, e2.z, e2.w};
    float x[4], y[4], z[4];
#pragma unroll
    for (int q = 0; q < 4; q++) {
        float s0, c0, s1, c1, s2, c2;
        __sincosf(t[3 * q + 0], &s0, &c0);
        __sincosf(t[3 * q + 1], &s1, &c1);
        __sincosf(t[3 * q + 2], &s2, &c2);
        float cc = c0 * c1;
        x[q] = cc * c2 - s0 * s2;
        y[q] = cc * s2 + s0 * c2;
        z[q] = -c0 * s1;
    }
    float z01   = z[0] * z[1];
    float z23   = z[2] * z[3];
    float z012  = z01 * z[2];
    float z123  = z[1] * z23;
    float z0123 = z01 * z23;
    float x01   = x[0] * x[1];

    float4 o;
    o.x = n0.x * x01           + n0.y * (x[0] * y[1] * z23)         + n0.z * z123;
    o.y = n0.w * (x[1] * x[2]) + n1.x * (z[0] * y[1] * x[2])        + n1.y * z01;
    o.z = n1.z * (x[2] * x[3]) + n1.w * (z01 * y[2] * x[3])         + n2.x * z012;
    o.w = n2.y * (x01 * x[3])  - n2.z * (y[0] * y[1] * z[2] * y[3]) + n2.w * z0123;
    return o;
}

__global__ __launch_bounds__(256, 6) void vqc_tma(const float4* __restrict__ enc,
                                                  const float* __restrict__ w,
                                                  float4* __restrict__ out,
                                                  int B) {
    __shared__ __align__(16) float4 buf[NSTAGE][TILE_VEC];   // 3 x 12 KB
    __shared__ __align__(16) float sn[12];
    __shared__ __align__(8) unsigned long long mbar[NSTAGE];

    const int tid = threadIdx.x;

    if (tid < 4) {
        int q = tid;
        float st, ct, sl, cl;
        __sincosf(w[q * 3 + 0], &st, &ct);
        __sincosf(w[q * 3 + 2], &sl, &cl);
        sn[q * 3 + 0] = -st * cl;
        sn[q * 3 + 1] =  st * sl;
        sn[q * 3 + 2] =  ct;
    }
    if (tid == 0) {
#pragma unroll
        for (int s = 0; s < NSTAGE; s++) mbar_init(smem_u32(&mbar[s]), 1);
    }
    __syncthreads();

    const float4* n4 = (const float4*)sn;
    const float4 n0 = n4[0], n1 = n4[1], n2 = n4[2];

    const int ntiles = B >> 8;            // full 256-item tiles
    const int bid = blockIdx.x, G = gridDim.x;
    // tiles for this block: t = bid + j*G, j = 0..nloc-1
    const int nloc = (bid < ntiles) ? (ntiles - bid - 1) / G + 1 : 0;

    // Prologue: fill all 3 stages.
    if (tid == 0) {
#pragma unroll
        for (int j = 0; j < NSTAGE; j++) {
            if (j < nloc) {
                int t = bid + j * G;
                mbar_expect_tx(smem_u32(&mbar[j]), TILE_BYTES);
                tma_bulk_g2s(smem_u32(&buf[j][0]), enc + (size_t)t * TILE_VEC,
                             TILE_BYTES, smem_u32(&mbar[j]));
            }
        }
    }

    for (int j = 0; j < nloc; j++) {
        const int s = j % NSTAGE;
        mbar_wait(smem_u32(&mbar[s]), (unsigned)((j / NSTAGE) & 1));

        const int t = bid + j * G;
        // Conflict-free LDS.128 x3: 48B stride -> disjoint banks per 8-thread phase.
        float4 e0 = buf[s][tid * 3 + 0];
        float4 e1 = buf[s][tid * 3 + 1];
        float4 e2 = buf[s][tid * 3 + 2];
        float4 o = vqc_one(e0, e1, e2, n0, n1, n2);
        __stcs(&out[t * TILE + tid], o);

        __syncthreads();   // whole block done reading stage s

        if (tid == 0 && j + NSTAGE < nloc) {
            int t2 = bid + (j + NSTAGE) * G;
            mbar_expect_tx(smem_u32(&mbar[s]), TILE_BYTES);
            tma_bulk_g2s(smem_u32(&buf[s][0]), enc + (size_t)t2 * TILE_VEC,
                         TILE_BYTES, smem_u32(&mbar[s]));
        }
    }

    // Remainder items (B % 256) — direct path, last block only.
    if (bid == G - 1) {
        for (int i = ntiles * TILE + tid; i < B; i += 256) {
            const float4* p = enc + 3 * i;
            float4 e0 = __ldcs(p + 0);
            float4 e1 = __ldcs(p + 1);
            float4 e2 = __ldcs(p + 2);
            __stcs(&out[i], vqc_one(e0, e1, e2, n0, n1, n2));
        }
    }
}

extern "C" void kernel_launch(void* const* d_in, const int* in_sizes, int n_in,
                              void* d_out, int out_size) {
    int ei = 0, wi = 1;
    if (n_in >= 2 && in_sizes[0] < in_sizes[1]) { ei = 1; wi = 0; }
    const float* enc = (const float*)d_in[ei];
    const float* w   = (const float*)d_in[wi];
    int B = in_sizes[ei] / 12;

    int ntiles = B >> 8;
    int max_blocks = 152 * 6;             // one resident wave (36KB smem class)
    int blocks = ntiles < max_blocks ? (ntiles > 0 ? ntiles : 1) : max_blocks;

    vqc_tma<<<blocks, 256>>>((const float4*)enc, w, (float4*)d_out, B);
}